// round 8
// baseline (speedup 1.0000x reference)
#include <cuda_runtime.h>
#include <cstdint>

// Problem: [8, 2048, 256] fp32 -> pairwise sq. distances [8, 2048, 2048]
#define BATCH 8
#define SEQ   2048
#define KDIM  256
#define BM    128
#define NT    (SEQ / BM)             // 16
#define NPAIR (NT * (NT + 1) / 2)    // 136 triangular tile pairs
#define BK    32                     // K floats per chunk
#define NCHUNK (KDIM / BK)           // 8
#define NSTAGE 3

#define PITCH      36                       // floats per smem row (144B)
#define TILE_F     (BM * PITCH)             // 4608 floats per tile
#define STAGE_F    (2 * TILE_F)             // A + B = 9216 floats per stage
#define SMEM_BYTES (NSTAGE * STAGE_F * 4)   // 110592 B (3 stages)
// epilogue transpose staging (128 x 132 = 16896 floats) aliases the stages

__device__ float g_norms[BATCH * SEQ];

// ---------------------------------------------------------------------------
// PTX helpers (sm_80-era only: must compile for plain compute_100)
// ---------------------------------------------------------------------------
__device__ __forceinline__ uint32_t smem_u32(const void* p) {
    uint32_t a;
    asm("{ .reg .u64 t; cvta.to.shared.u64 t, %1; cvt.u32.u64 %0, t; }"
        : "=r"(a) : "l"(p));
    return a;
}
__device__ __forceinline__ void cp16(uint32_t dst, const void* src) {
    asm volatile("cp.async.cg.shared.global [%0], [%1], 16;"
                 :: "r"(dst), "l"(src) : "memory");
}
#define CP_COMMIT() asm volatile("cp.async.commit_group;" ::: "memory")
#define CP_WAIT(n)  asm volatile("cp.async.wait_group %0;" :: "n"(n) : "memory")

__device__ __forceinline__ void ldsm_x4(uint32_t addr, uint32_t* r) {
    asm volatile("ldmatrix.sync.aligned.m8n8.x4.shared.b16 {%0,%1,%2,%3}, [%4];"
                 : "=r"(r[0]), "=r"(r[1]), "=r"(r[2]), "=r"(r[3]) : "r"(addr));
}
__device__ __forceinline__ void ldsm_x2(uint32_t addr, uint32_t* r) {
    asm volatile("ldmatrix.sync.aligned.m8n8.x2.shared.b16 {%0,%1}, [%2];"
                 : "=r"(r[0]), "=r"(r[1]) : "r"(addr));
}

// mma tf32: operands carry raw fp32 bits (HW truncates to tf32 mantissa)
__device__ __forceinline__ void mma_tf32(float* c, const uint32_t* a,
                                         const uint32_t* b) {
    asm volatile(
        "mma.sync.aligned.m16n8k8.row.col.f32.tf32.tf32.f32 "
        "{%0,%1,%2,%3}, {%4,%5,%6,%7}, {%8,%9}, {%0,%1,%2,%3};"
        : "+f"(c[0]), "+f"(c[1]), "+f"(c[2]), "+f"(c[3])
        : "r"(a[0]), "r"(a[1]), "r"(a[2]), "r"(a[3]), "r"(b[0]), "r"(b[1]));
}

// ---------------------------------------------------------------------------
// Kernel 1: per-row squared norms (fp32 exact)
// ---------------------------------------------------------------------------
__global__ void norms_kernel(const float* __restrict__ x) {
    int row  = blockIdx.x * 8 + (threadIdx.x >> 5);
    int lane = threadIdx.x & 31;
    if (row >= BATCH * SEQ) return;
    const float4* p = (const float4*)(x + (size_t)row * KDIM);
    float s = 0.f;
#pragma unroll
    for (int i = 0; i < 2; i++) {
        float4 v = p[lane + 32 * i];
        s += v.x * v.x + v.y * v.y + v.z * v.z + v.w * v.w;
    }
#pragma unroll
    for (int o = 16; o; o >>= 1) s += __shfl_xor_sync(0xffffffffu, s, o);
    if (lane == 0) g_norms[row] = s;
}

// ---------------------------------------------------------------------------
// Kernel 2: tf32 mma.sync Gram + distance epilogue, symmetric tile pairs.
// 256 threads, warp grid 2(M) x 4(N), warp tile 64x32, mma m16n8k8.
// 3-stage cp.async pipeline, ONE barrier per chunk, prefetch before compute.
// ---------------------------------------------------------------------------
__global__ __launch_bounds__(256, 2)
void dist_mma(const float* __restrict__ x, float* __restrict__ out) {
    extern __shared__ float smf[];
    __shared__ float s_ni[BM], s_nj[BM];
    const uint32_t smb = smem_u32(smf);

    const int tid  = threadIdx.x;
    const int lane = tid & 31;
    const int w    = tid >> 5;
    const int wm   = w & 1;          // warp row (2 x 64)
    const int wn   = w >> 1;         // warp col (4 x 32)
    const int gid  = lane >> 2;      // 0..7
    const int tig  = lane & 3;       // 0..3

    // ldmatrix per-lane address offsets (bytes), within a fragment
    const uint32_t aoff = (uint32_t)(((lane & 15) * PITCH + 4 * (lane >> 4)) * 4);
    const uint32_t boff = (uint32_t)(((lane & 7) * PITCH + 4 * ((lane >> 3) & 1)) * 4);

    const int b = blockIdx.y;
    int p = blockIdx.x;
    int ti = 0;
    while (p >= NT - ti) { p -= NT - ti; ti++; }
    const int tj = ti + p;
    const int i0 = ti * BM, j0 = tj * BM;
    const bool diag = (ti == tj);

    const float* xb = x + (size_t)b * SEQ * KDIM;
    float* ob = out + (size_t)b * SEQ * SEQ;

    // preload norms into static smem (published by first loop barrier)
    if (tid < BM) s_ni[tid] = g_norms[b * SEQ + i0 + tid];
    else          s_nj[tid - BM] = g_norms[b * SEQ + j0 + tid - BM];

    // chunk loader: A tile rows i0.., B tile rows j0.., both [row][k] pitch 36
    auto load_chunk = [&](int c, int s) {
        const uint32_t base = smb + (uint32_t)s * (STAGE_F * 4);
#pragma unroll
        for (int t = 0; t < 4; t++) {
            const int idx = tid + t * 256;          // 1024 granules per tile
            const int row = idx >> 3;
            const int g   = idx & 7;
            const uint32_t off = (uint32_t)(row * (PITCH * 4) + g * 16);
            cp16(base + off,
                 xb + (size_t)(i0 + row) * KDIM + c * BK + g * 4);
            cp16(base + TILE_F * 4 + off,
                 xb + (size_t)(j0 + row) * KDIM + c * BK + g * 4);
        }
        CP_COMMIT();
    };

    float acc[4][4][4];
#pragma unroll
    for (int mt = 0; mt < 4; mt++)
#pragma unroll
        for (int nt = 0; nt < 4; nt++)
#pragma unroll
            for (int q = 0; q < 4; q++) acc[mt][nt][q] = 0.f;

    load_chunk(0, 0);
    load_chunk(1, 1);

    for (int c = 0; c < NCHUNK; c++) {
        // chunk c must be resident; at most one younger group may stay pending
        if (c < NCHUNK - 1) { CP_WAIT(1); } else { CP_WAIT(0); }
        __syncthreads();   // also proves: stage (c+2)%3 readers (chunk c-1) done

        if (c + 2 < NCHUNK) load_chunk(c + 2, (c + 2) % NSTAGE);

        const uint32_t As_u = smb +
            (uint32_t)(((c % NSTAGE) * STAGE_F + wm * 64 * PITCH) * 4) + aoff;
        const uint32_t Bs_u = smb +
            (uint32_t)(((c % NSTAGE) * STAGE_F + TILE_F + wn * 32 * PITCH) * 4) + boff;

#pragma unroll
        for (int kk = 0; kk < 4; kk++) {
            uint32_t af[4][4], bf[4][2];
#pragma unroll
            for (int mt = 0; mt < 4; mt++)
                ldsm_x4(As_u + (uint32_t)((mt * 16 * PITCH + kk * 8) * 4),
                        af[mt]);
#pragma unroll
            for (int nt = 0; nt < 4; nt++)
                ldsm_x2(Bs_u + (uint32_t)((nt * 8 * PITCH + kk * 8) * 4),
                        bf[nt]);
#pragma unroll
            for (int mt = 0; mt < 4; mt++)
#pragma unroll
                for (int nt = 0; nt < 4; nt++)
                    mma_tf32(acc[mt][nt], af[mt], bf[nt]);
        }
    }

    __syncthreads();   // all compute done before staging smem is repurposed

    // -----------------------------------------------------------------------
    // Epilogue. Fragment (mt,nt): rows r0/r0+8, cols jc/jc+1.
    // Normal tile: direct float2 stores. Mirror: transpose-stage into the
    // (dead) pipeline smem [col][row] pitch 132, then coalesced float4 out.
    // -----------------------------------------------------------------------
    float* sd = smf;   // 128 x 132 floats = 16896, well within stage area
#pragma unroll
    for (int mt = 0; mt < 4; mt++) {
        const int r0 = wm * 64 + mt * 16 + gid;
        const int r1 = r0 + 8;
        const float n0 = s_ni[r0], n1 = s_ni[r1];
#pragma unroll
        for (int nt = 0; nt < 4; nt++) {
            const int jc = wn * 32 + nt * 8 + tig * 2;
            const float m0 = s_nj[jc], m1 = s_nj[jc + 1];
            float d00 = fmaxf(n0 + m0 - 2.f * acc[mt][nt][0], 0.f);
            float d01 = fmaxf(n0 + m1 - 2.f * acc[mt][nt][1], 0.f);
            float d10 = fmaxf(n1 + m0 - 2.f * acc[mt][nt][2], 0.f);
            float d11 = fmaxf(n1 + m1 - 2.f * acc[mt][nt][3], 0.f);
            if (diag) {
                if (r0 == jc)     d00 = 0.f;
                if (r0 == jc + 1) d01 = 0.f;
                if (r1 == jc)     d10 = 0.f;
                if (r1 == jc + 1) d11 = 0.f;
            }
            *(float2*)(ob + (size_t)(i0 + r0) * SEQ + j0 + jc) =
                make_float2(d00, d01);
            *(float2*)(ob + (size_t)(i0 + r1) * SEQ + j0 + jc) =
                make_float2(d10, d11);
            if (!diag) {
                sd[jc * 132 + r0]       = d00;
                sd[(jc + 1) * 132 + r0] = d01;
                sd[jc * 132 + r1]       = d10;
                sd[(jc + 1) * 132 + r1] = d11;
            }
        }
    }

    if (!diag) {
        __syncthreads();
        const int jr = tid >> 1;            // mirror row 0..127
        const int h  = tid & 1;             // half: 64 floats
        const float4* srow = (const float4*)(sd + jr * 132 + h * 64);
        float4* drow = (float4*)(ob + (size_t)(j0 + jr) * SEQ + i0 + h * 64);
#pragma unroll
        for (int q = 0; q < 16; q++) drow[q] = srow[q];
    }
}

// ---------------------------------------------------------------------------
extern "C" void kernel_launch(void* const* d_in, const int* in_sizes, int n_in,
                              void* d_out, int out_size) {
    const float* x = (const float*)d_in[0];
    float* out = (float*)d_out;
    (void)in_sizes; (void)n_in; (void)out_size;

    cudaFuncSetAttribute(dist_mma, cudaFuncAttributeMaxDynamicSharedMemorySize,
                         SMEM_BYTES);
    norms_kernel<<<(BATCH * SEQ + 7) / 8, 256>>>(x);
    dist_mma<<<dim3(NPAIR, BATCH), 256, SMEM_BYTES>>>(x, out);
}

// round 9
// speedup vs baseline: 1.1001x; 1.1001x over previous
#include <cuda_runtime.h>
#include <cstdint>

// Problem: [8, 2048, 256] fp32 -> pairwise sq. distances [8, 2048, 2048]
#define BATCH 8
#define SEQ   2048
#define KDIM  256
#define BM    128
#define NT    (SEQ / BM)             // 16
#define NPAIR (NT * (NT + 1) / 2)    // 136 triangular tile pairs
#define NWORK (NPAIR * BATCH)        // 1088 work items
#define GRID_P 296                   // persistent: 148 SMs x 2 CTAs
#define BK    32                     // K floats per chunk
#define NCHUNK (KDIM / BK)           // 8

#define PITCH      36                       // floats per smem row (144B)
#define TILE_F     (BM * PITCH)             // 4608 floats per tile
#define STAGE_F    (2 * TILE_F)             // A + B = 9216 floats per stage
#define SMEM_BYTES (2 * STAGE_F * 4)        // 73728 B (2 stages)
#define OPITCH 132                          // epilogue staging pitch (floats)
// epilogue staging (128 x 132 = 67.6KB) aliases the dead pipeline stages

__device__ float g_norms[BATCH * SEQ];

// ---------------------------------------------------------------------------
// PTX helpers (sm_80-era only: must compile for plain compute_100)
// ---------------------------------------------------------------------------
__device__ __forceinline__ uint32_t smem_u32(const void* p) {
    uint32_t a;
    asm("{ .reg .u64 t; cvta.to.shared.u64 t, %1; cvt.u32.u64 %0, t; }"
        : "=r"(a) : "l"(p));
    return a;
}
__device__ __forceinline__ void cp16(uint32_t dst, const void* src) {
    asm volatile("cp.async.cg.shared.global [%0], [%1], 16;"
                 :: "r"(dst), "l"(src) : "memory");
}
#define CP_COMMIT() asm volatile("cp.async.commit_group;" ::: "memory")
#define CP_WAIT(n)  asm volatile("cp.async.wait_group %0;" :: "n"(n) : "memory")

__device__ __forceinline__ void ldsm_x4(uint32_t addr, uint32_t* r) {
    asm volatile("ldmatrix.sync.aligned.m8n8.x4.shared.b16 {%0,%1,%2,%3}, [%4];"
                 : "=r"(r[0]), "=r"(r[1]), "=r"(r[2]), "=r"(r[3]) : "r"(addr));
}

// mma tf32: operands carry raw fp32 bits (HW truncates to tf32 mantissa)
__device__ __forceinline__ void mma_tf32(float* c, const uint32_t* a,
                                         const uint32_t* b) {
    asm volatile(
        "mma.sync.aligned.m16n8k8.row.col.f32.tf32.tf32.f32 "
        "{%0,%1,%2,%3}, {%4,%5,%6,%7}, {%8,%9}, {%0,%1,%2,%3};"
        : "+f"(c[0]), "+f"(c[1]), "+f"(c[2]), "+f"(c[3])
        : "r"(a[0]), "r"(a[1]), "r"(a[2]), "r"(a[3]), "r"(b[0]), "r"(b[1]));
}

// ---------------------------------------------------------------------------
// Kernel 1: per-row squared norms (fp32 exact)
// ---------------------------------------------------------------------------
__global__ void norms_kernel(const float* __restrict__ x) {
    int row  = blockIdx.x * 8 + (threadIdx.x >> 5);
    int lane = threadIdx.x & 31;
    if (row >= BATCH * SEQ) return;
    const float4* p = (const float4*)(x + (size_t)row * KDIM);
    float s = 0.f;
#pragma unroll
    for (int i = 0; i < 2; i++) {
        float4 v = p[lane + 32 * i];
        s += v.x * v.x + v.y * v.y + v.z * v.z + v.w * v.w;
    }
#pragma unroll
    for (int o = 16; o; o >>= 1) s += __shfl_xor_sync(0xffffffffu, s, o);
    if (lane == 0) g_norms[row] = s;
}

// ---------------------------------------------------------------------------
// Kernel 2: persistent tf32 mma.sync Gram + distance epilogue.
// 256 threads, warp grid 2(M) x 4(N), warp tile 64x32, mma m16n8k8.
// 2-stage cp.async pipeline (R7 structure). Epilogue: both tile orientations
// staged through smem, written warp-per-row with coalesced STG.128.
// ---------------------------------------------------------------------------
__global__ __launch_bounds__(256, 2)
void dist_mma(const float* __restrict__ x, float* __restrict__ out) {
    extern __shared__ float smf[];
    __shared__ float s_ni[BM], s_nj[BM];
    const uint32_t smb = smem_u32(smf);

    const int tid  = threadIdx.x;
    const int lane = tid & 31;
    const int w    = tid >> 5;
    const int wm   = w & 1;          // warp row (2 x 64)
    const int wn   = w >> 1;         // warp col (4 x 32)
    const int gid  = lane >> 2;      // 0..7
    const int tig  = lane & 3;       // 0..3

    // ldmatrix per-lane address offsets (bytes)
    const uint32_t aoff = (uint32_t)(((lane & 15) * PITCH + 4 * (lane >> 4)) * 4);
    // B x4: lanes 0-7 -> (row, k0), 8-15 -> (row, k4), 16-23 -> (row+8, k0),
    //       24-31 -> (row+8, k4)  => regs {b[nt][0], b[nt][1], b[nt+1][0], b[nt+1][1]}
    const uint32_t boff4 = (uint32_t)(
        (((lane & 7) + 8 * ((lane >> 4) & 1)) * PITCH + 4 * ((lane >> 3) & 1)) * 4);

    for (int work = blockIdx.x; work < NWORK; work += GRID_P) {
        const int b = work / NPAIR;
        int p = work % NPAIR;
        int ti = 0;
        while (p >= NT - ti) { p -= NT - ti; ti++; }
        const int tj = ti + p;
        const int i0 = ti * BM, j0 = tj * BM;
        const bool diag = (ti == tj);

        const float* xb = x + (size_t)b * SEQ * KDIM;
        float* ob = out + (size_t)b * SEQ * SEQ;

        // norms preload (consumed in epilogue, after syncs)
        if (tid < BM) s_ni[tid] = g_norms[b * SEQ + i0 + tid];
        else          s_nj[tid - BM] = g_norms[b * SEQ + j0 + tid - BM];

        auto load_chunk = [&](int c, int s) {
            const uint32_t base = smb + (uint32_t)s * (STAGE_F * 4);
#pragma unroll
            for (int t = 0; t < 4; t++) {
                const int idx = tid + t * 256;
                const int row = idx >> 3;
                const int g   = idx & 7;
                const uint32_t off = (uint32_t)(row * (PITCH * 4) + g * 16);
                cp16(base + off,
                     xb + (size_t)(i0 + row) * KDIM + c * BK + g * 4);
                cp16(base + TILE_F * 4 + off,
                     xb + (size_t)(j0 + row) * KDIM + c * BK + g * 4);
            }
            CP_COMMIT();
        };

        float acc[4][4][4];
#pragma unroll
        for (int mt = 0; mt < 4; mt++)
#pragma unroll
            for (int nt = 0; nt < 4; nt++)
#pragma unroll
                for (int q = 0; q < 4; q++) acc[mt][nt][q] = 0.f;

        load_chunk(0, 0);
        load_chunk(1, 1);

        for (int c = 0; c < NCHUNK; c++) {
            if (c < NCHUNK - 1) { CP_WAIT(1); } else { CP_WAIT(0); }
            __syncthreads();

            const uint32_t As_u = smb +
                (uint32_t)(((c & 1) * STAGE_F + wm * 64 * PITCH) * 4) + aoff;
            const uint32_t Bs_u = smb +
                (uint32_t)(((c & 1) * STAGE_F + TILE_F + wn * 32 * PITCH) * 4) + boff4;

#pragma unroll
            for (int kk = 0; kk < 4; kk++) {
                uint32_t af[4][4], bf[4][2];
#pragma unroll
                for (int mt = 0; mt < 4; mt++)
                    ldsm_x4(As_u + (uint32_t)((mt * 16 * PITCH + kk * 8) * 4),
                            af[mt]);
#pragma unroll
                for (int nt = 0; nt < 4; nt += 2) {
                    uint32_t r4[4];
                    ldsm_x4(Bs_u + (uint32_t)((nt * 8 * PITCH + kk * 8) * 4), r4);
                    bf[nt][0]     = r4[0];
                    bf[nt][1]     = r4[1];
                    bf[nt + 1][0] = r4[2];
                    bf[nt + 1][1] = r4[3];
                }
#pragma unroll
                for (int mt = 0; mt < 4; mt++)
#pragma unroll
                    for (int nt = 0; nt < 4; nt++)
                        mma_tf32(acc[mt][nt], af[mt], bf[nt]);
            }
            __syncthreads();
            if (c + 2 < NCHUNK) load_chunk(c + 2, c & 1);
        }

        // ------------------------------------------------------------------
        // Convert acc -> distances in place (diag zeroed)
        // ------------------------------------------------------------------
#pragma unroll
        for (int mt = 0; mt < 4; mt++) {
            const int r0 = wm * 64 + mt * 16 + gid;
            const int r1 = r0 + 8;
            const float n0 = s_ni[r0], n1 = s_ni[r1];
#pragma unroll
            for (int nt = 0; nt < 4; nt++) {
                const int jc = wn * 32 + nt * 8 + tig * 2;
                const float m0 = s_nj[jc], m1 = s_nj[jc + 1];
                float d00 = fmaxf(n0 + m0 - 2.f * acc[mt][nt][0], 0.f);
                float d01 = fmaxf(n0 + m1 - 2.f * acc[mt][nt][1], 0.f);
                float d10 = fmaxf(n1 + m0 - 2.f * acc[mt][nt][2], 0.f);
                float d11 = fmaxf(n1 + m1 - 2.f * acc[mt][nt][3], 0.f);
                if (diag) {
                    if (r0 == jc)     d00 = 0.f;
                    if (r0 == jc + 1) d01 = 0.f;
                    if (r1 == jc)     d10 = 0.f;
                    if (r1 == jc + 1) d11 = 0.f;
                }
                acc[mt][nt][0] = d00; acc[mt][nt][1] = d01;
                acc[mt][nt][2] = d10; acc[mt][nt][3] = d11;
            }
        }

        // ------------------------------------------------------------------
        // Pass 1: normal orientation. Stage sn[row][col], write coalesced.
        // ------------------------------------------------------------------
        float* sn = smf;   // 128 x 132 floats, aliases dead pipeline stages
#pragma unroll
        for (int mt = 0; mt < 4; mt++) {
            const int r0 = wm * 64 + mt * 16 + gid;
#pragma unroll
            for (int nt = 0; nt < 4; nt++) {
                const int jc = wn * 32 + nt * 8 + tig * 2;
                *(float2*)(sn + r0 * OPITCH + jc) =
                    make_float2(acc[mt][nt][0], acc[mt][nt][1]);
                *(float2*)(sn + (r0 + 8) * OPITCH + jc) =
                    make_float2(acc[mt][nt][2], acc[mt][nt][3]);
            }
        }
        __syncthreads();
#pragma unroll
        for (int rr = 0; rr < 16; rr++) {
            const int row = w * 16 + rr;
            float4 v = *(const float4*)(sn + row * OPITCH + lane * 4);
            *(float4*)(ob + (size_t)(i0 + row) * SEQ + j0 + lane * 4) = v;
        }

        // ------------------------------------------------------------------
        // Pass 2: mirror orientation (transposed staging), skip on diagonal.
        // ------------------------------------------------------------------
        if (!diag) {
            __syncthreads();   // pass-1 reads done before overwrite
#pragma unroll
            for (int mt = 0; mt < 4; mt++) {
                const int r0 = wm * 64 + mt * 16 + gid;
#pragma unroll
                for (int nt = 0; nt < 4; nt++) {
                    const int jc = wn * 32 + nt * 8 + tig * 2;
                    sn[jc * OPITCH + r0]           = acc[mt][nt][0];
                    sn[(jc + 1) * OPITCH + r0]     = acc[mt][nt][1];
                    sn[jc * OPITCH + r0 + 8]       = acc[mt][nt][2];
                    sn[(jc + 1) * OPITCH + r0 + 8] = acc[mt][nt][3];
                }
            }
            __syncthreads();
#pragma unroll
            for (int rr = 0; rr < 16; rr++) {
                const int row = w * 16 + rr;
                float4 v = *(const float4*)(sn + row * OPITCH + lane * 4);
                *(float4*)(ob + (size_t)(j0 + row) * SEQ + i0 + lane * 4) = v;
            }
        }

        __syncthreads();   // staging + s_ni/s_nj reads done before next item
    }
}

// ---------------------------------------------------------------------------
extern "C" void kernel_launch(void* const* d_in, const int* in_sizes, int n_in,
                              void* d_out, int out_size) {
    const float* x = (const float*)d_in[0];
    float* out = (float*)d_out;
    (void)in_sizes; (void)n_in; (void)out_size;

    cudaFuncSetAttribute(dist_mma, cudaFuncAttributeMaxDynamicSharedMemorySize,
                         SMEM_BYTES);
    norms_kernel<<<(BATCH * SEQ + 7) / 8, 256>>>(x);
    dist_mma<<<GRID_P, 256, SMEM_BYTES>>>(x, out);
}

// round 11
// speedup vs baseline: 1.5660x; 1.4236x over previous
#include <cuda_runtime.h>
#include <cuda_bf16.h>
#include <cstdint>

// Problem: [8, 2048, 256] fp32 -> pairwise sq. distances [8, 2048, 2048]
#define BATCH 8
#define SEQ   2048
#define KDIM  256
#define BM    128
#define NT    (SEQ / BM)             // 16
#define NPAIR (NT * (NT + 1) / 2)    // 136 triangular tile pairs
#define NWORK (NPAIR * BATCH)        // 1088 work items
#define GRID_P 296                   // persistent: 148 SMs x 2 CTAs
#define BK    64                     // K halves per chunk (128B rows)
#define NCHUNK (KDIM / BK)           // 4

#define PITCH_H    72                        // halves per smem row (144B)
#define ROW_B      144                       // bytes per smem row
#define TILE_B     (BM * ROW_B)              // 18432 B per tile
#define STAGE_B    (2 * TILE_B)              // A + B = 36864 B per stage
#define SMEM_BYTES (2 * STAGE_B)             // 73728 B (2 stages)
#define OPITCH 132                           // epilogue staging pitch (floats)
// epilogue staging (128 x 132 fp32 = 67.6KB) aliases the dead pipeline stages

__device__ float          g_norms[BATCH * SEQ];
__device__ __nv_bfloat16  g_xbf[BATCH * SEQ * KDIM];   // 8.4 MB bf16 copy

// ---------------------------------------------------------------------------
// PTX helpers (sm_80-era only: must compile for plain compute_100)
// ---------------------------------------------------------------------------
__device__ __forceinline__ uint32_t smem_u32(const void* p) {
    uint32_t a;
    asm("{ .reg .u64 t; cvta.to.shared.u64 t, %1; cvt.u32.u64 %0, t; }"
        : "=r"(a) : "l"(p));
    return a;
}
__device__ __forceinline__ void cp16(uint32_t dst, const void* src) {
    asm volatile("cp.async.cg.shared.global [%0], [%1], 16;"
                 :: "r"(dst), "l"(src) : "memory");
}
#define CP_COMMIT() asm volatile("cp.async.commit_group;" ::: "memory")
#define CP_WAIT(n)  asm volatile("cp.async.wait_group %0;" :: "n"(n) : "memory")

__device__ __forceinline__ void ldsm_x4(uint32_t addr, uint32_t* r) {
    asm volatile("ldmatrix.sync.aligned.m8n8.x4.shared.b16 {%0,%1,%2,%3}, [%4];"
                 : "=r"(r[0]), "=r"(r[1]), "=r"(r[2]), "=r"(r[3]) : "r"(addr));
}

__device__ __forceinline__ void mma_bf16(float* c, const uint32_t* a,
                                         const uint32_t* b) {
    asm volatile(
        "mma.sync.aligned.m16n8k16.row.col.f32.bf16.bf16.f32 "
        "{%0,%1,%2,%3}, {%4,%5,%6,%7}, {%8,%9}, {%0,%1,%2,%3};"
        : "+f"(c[0]), "+f"(c[1]), "+f"(c[2]), "+f"(c[3])
        : "r"(a[0]), "r"(a[1]), "r"(a[2]), "r"(a[3]), "r"(b[0]), "r"(b[1]));
}

// ---------------------------------------------------------------------------
// Kernel 1: per-row squared norms (fp32 exact) + bf16 conversion (RN)
// One warp per row; lane handles 8 contiguous floats (float4 pair).
// ---------------------------------------------------------------------------
__global__ void norms_conv_kernel(const float* __restrict__ x) {
    int row  = blockIdx.x * 8 + (threadIdx.x >> 5);
    int lane = threadIdx.x & 31;
    if (row >= BATCH * SEQ) return;
    const float4* p = (const float4*)(x + (size_t)row * KDIM);
    float4 v0 = p[2 * lane];
    float4 v1 = p[2 * lane + 1];
    float s = v0.x * v0.x + v0.y * v0.y + v0.z * v0.z + v0.w * v0.w +
              v1.x * v1.x + v1.y * v1.y + v1.z * v1.z + v1.w * v1.w;

    __nv_bfloat162 h[4];
    h[0] = __floats2bfloat162_rn(v0.x, v0.y);
    h[1] = __floats2bfloat162_rn(v0.z, v0.w);
    h[2] = __floats2bfloat162_rn(v1.x, v1.y);
    h[3] = __floats2bfloat162_rn(v1.z, v1.w);
    *(uint4*)(g_xbf + (size_t)row * KDIM + lane * 8) = *(const uint4*)h;

#pragma unroll
    for (int o = 16; o; o >>= 1) s += __shfl_xor_sync(0xffffffffu, s, o);
    if (lane == 0) g_norms[row] = s;
}

// ---------------------------------------------------------------------------
// Kernel 2: persistent bf16 mma.sync Gram + fp32 distance epilogue.
// 256 threads, warp grid 2(M) x 4(N), warp tile 64x32, mma m16n8k16.
// 2-stage cp.async pipeline, BK=64 (4 chunks).
// ---------------------------------------------------------------------------
__global__ __launch_bounds__(256, 2)
void dist_mma(float* __restrict__ out) {
    extern __shared__ float smf[];
    __shared__ float s_ni[BM], s_nj[BM];
    const uint32_t smb = smem_u32(smf);

    const int tid  = threadIdx.x;
    const int lane = tid & 31;
    const int w    = tid >> 5;
    const int wm   = w & 1;          // warp row (2 x 64)
    const int wn   = w >> 1;         // warp col (4 x 32)
    const int gid  = lane >> 2;      // 0..7
    const int tig  = lane & 3;       // 0..3

    // ldmatrix per-lane address offsets (bytes), b16 element space
    // A x4: lanes 0-15 -> row (lane&15), k0 ; 16-31 -> same row, k8
    const uint32_t aoff = (uint32_t)(
        ((lane & 15) * PITCH_H + ((lane >> 4) & 1) * 8) * 2);
    // B x4: lanes 0-7 -> col lane k0; 8-15 -> col k8; 16-23 -> col+8 k0; 24-31 -> col+8 k8
    const uint32_t boff4 = (uint32_t)(
        (((lane & 7) + 8 * ((lane >> 4) & 1)) * PITCH_H +
         ((lane >> 3) & 1) * 8) * 2);

    for (int work = blockIdx.x; work < NWORK; work += GRID_P) {
        const int b = work / NPAIR;
        int p = work % NPAIR;
        int ti = 0;
        while (p >= NT - ti) { p -= NT - ti; ti++; }
        const int tj = ti + p;
        const int i0 = ti * BM, j0 = tj * BM;
        const bool diag = (ti == tj);

        const __nv_bfloat16* xb = g_xbf + (size_t)b * SEQ * KDIM;
        float* ob = out + (size_t)b * SEQ * SEQ;

        if (tid < BM) s_ni[tid] = g_norms[b * SEQ + i0 + tid];
        else          s_nj[tid - BM] = g_norms[b * SEQ + j0 + tid - BM];

        // chunk loader: 128 rows x 8 granules (16B = 8 halves) per tile
        auto load_chunk = [&](int c, int s) {
            const uint32_t base = smb + (uint32_t)s * STAGE_B;
#pragma unroll
            for (int t = 0; t < 4; t++) {
                const int idx = tid + t * 256;
                const int row = idx >> 3;
                const int g   = idx & 7;
                const uint32_t off = (uint32_t)(row * ROW_B + g * 16);
                cp16(base + off,
                     xb + (size_t)(i0 + row) * KDIM + c * BK + g * 8);
                cp16(base + TILE_B + off,
                     xb + (size_t)(j0 + row) * KDIM + c * BK + g * 8);
            }
            CP_COMMIT();
        };

        float acc[4][4][4];
#pragma unroll
        for (int mt = 0; mt < 4; mt++)
#pragma unroll
            for (int nt = 0; nt < 4; nt++)
#pragma unroll
                for (int q = 0; q < 4; q++) acc[mt][nt][q] = 0.f;

        load_chunk(0, 0);
        load_chunk(1, 1);

        for (int c = 0; c < NCHUNK; c++) {
            if (c < NCHUNK - 1) { CP_WAIT(1); } else { CP_WAIT(0); }
            __syncthreads();

            const uint32_t As_u = smb +
                (uint32_t)((c & 1) * STAGE_B + wm * 64 * ROW_B) + aoff;
            const uint32_t Bs_u = smb +
                (uint32_t)((c & 1) * STAGE_B + TILE_B + wn * 32 * ROW_B) + boff4;

#pragma unroll
            for (int kk = 0; kk < 4; kk++) {   // 4 x K=16 covers BK=64
                uint32_t af[4][4], bf[4][2];
#pragma unroll
                for (int mt = 0; mt < 4; mt++)
                    ldsm_x4(As_u + (uint32_t)(mt * 16 * ROW_B + kk * 32),
                            af[mt]);
#pragma unroll
                for (int nt = 0; nt < 4; nt += 2) {
                    uint32_t r4[4];
                    ldsm_x4(Bs_u + (uint32_t)(nt * 8 * ROW_B + kk * 32), r4);
                    bf[nt][0]     = r4[0];
                    bf[nt][1]     = r4[1];
                    bf[nt + 1][0] = r4[2];
                    bf[nt + 1][1] = r4[3];
                }
#pragma unroll
                for (int mt = 0; mt < 4; mt++)
#pragma unroll
                    for (int nt = 0; nt < 4; nt++)
                        mma_bf16(acc[mt][nt], af[mt], bf[nt]);
            }
            __syncthreads();
            if (c + 2 < NCHUNK) load_chunk(c + 2, c & 1);
        }

        // ------------------------------------------------------------------
        // acc -> distances in place (diag zeroed)
        // ------------------------------------------------------------------
#pragma unroll
        for (int mt = 0; mt < 4; mt++) {
            const int r0 = wm * 64 + mt * 16 + gid;
            const int r1 = r0 + 8;
            const float n0 = s_ni[r0], n1 = s_ni[r1];
#pragma unroll
            for (int nt = 0; nt < 4; nt++) {
                const int jc = wn * 32 + nt * 8 + tig * 2;
                const float m0 = s_nj[jc], m1 = s_nj[jc + 1];
                float d00 = fmaxf(n0 + m0 - 2.f * acc[mt][nt][0], 0.f);
                float d01 = fmaxf(n0 + m1 - 2.f * acc[mt][nt][1], 0.f);
                float d10 = fmaxf(n1 + m0 - 2.f * acc[mt][nt][2], 0.f);
                float d11 = fmaxf(n1 + m1 - 2.f * acc[mt][nt][3], 0.f);
                if (diag) {
                    if (r0 == jc)     d00 = 0.f;
                    if (r0 == jc + 1) d01 = 0.f;
                    if (r1 == jc)     d10 = 0.f;
                    if (r1 == jc + 1) d11 = 0.f;
                }
                acc[mt][nt][0] = d00; acc[mt][nt][1] = d01;
                acc[mt][nt][2] = d10; acc[mt][nt][3] = d11;
            }
        }

        // ------------------------------------------------------------------
        // Pass 1: normal orientation via smem staging, coalesced STG.128
        // ------------------------------------------------------------------
        float* sn = smf;   // 128 x 132 fp32, aliases dead pipeline stages
#pragma unroll
        for (int mt = 0; mt < 4; mt++) {
            const int r0 = wm * 64 + mt * 16 + gid;
#pragma unroll
            for (int nt = 0; nt < 4; nt++) {
                const int jc = wn * 32 + nt * 8 + tig * 2;
                *(float2*)(sn + r0 * OPITCH + jc) =
                    make_float2(acc[mt][nt][0], acc[mt][nt][1]);
                *(float2*)(sn + (r0 + 8) * OPITCH + jc) =
                    make_float2(acc[mt][nt][2], acc[mt][nt][3]);
            }
        }
        __syncthreads();
#pragma unroll
        for (int rr = 0; rr < 16; rr++) {
            const int row = w * 16 + rr;
            float4 v = *(const float4*)(sn + row * OPITCH + lane * 4);
            *(float4*)(ob + (size_t)(i0 + row) * SEQ + j0 + lane * 4) = v;
        }

        // ------------------------------------------------------------------
        // Pass 2: mirror orientation (transposed staging), skip on diagonal
        // ------------------------------------------------------------------
        if (!diag) {
            __syncthreads();
#pragma unroll
            for (int mt = 0; mt < 4; mt++) {
                const int r0 = wm * 64 + mt * 16 + gid;
#pragma unroll
                for (int nt = 0; nt < 4; nt++) {
                    const int jc = wn * 32 + nt * 8 + tig * 2;
                    sn[jc * OPITCH + r0]           = acc[mt][nt][0];
                    sn[(jc + 1) * OPITCH + r0]     = acc[mt][nt][1];
                    sn[jc * OPITCH + r0 + 8]       = acc[mt][nt][2];
                    sn[(jc + 1) * OPITCH + r0 + 8] = acc[mt][nt][3];
                }
            }
            __syncthreads();
#pragma unroll
            for (int rr = 0; rr < 16; rr++) {
                const int row = w * 16 + rr;
                float4 v = *(const float4*)(sn + row * OPITCH + lane * 4);
                *(float4*)(ob + (size_t)(j0 + row) * SEQ + i0 + lane * 4) = v;
            }
        }

        __syncthreads();   // staging + norms reads done before next work item
    }
}

// ---------------------------------------------------------------------------
extern "C" void kernel_launch(void* const* d_in, const int* in_sizes, int n_in,
                              void* d_out, int out_size) {
    const float* x = (const float*)d_in[0];
    float* out = (float*)d_out;
    (void)in_sizes; (void)n_in; (void)out_size;

    cudaFuncSetAttribute(dist_mma, cudaFuncAttributeMaxDynamicSharedMemorySize,
                         SMEM_BYTES);
    norms_conv_kernel<<<(BATCH * SEQ + 7) / 8, 256>>>(x);
    dist_mma<<<GRID_P, 256, SMEM_BYTES>>>(out);
}

// round 12
// speedup vs baseline: 1.6157x; 1.0317x over previous
#include <cuda_runtime.h>
#include <cuda_bf16.h>
#include <cstdint>

// Problem: [8, 2048, 256] fp32 -> pairwise sq. distances [8, 2048, 2048]
#define BATCH 8
#define SEQ   2048
#define KDIM  256
#define BM    128
#define NT    (SEQ / BM)             // 16
#define NPAIR (NT * (NT + 1) / 2)    // 136 triangular tile pairs
#define NWORK (NPAIR * BATCH)        // 1088 work items
#define GRID_P 296                   // persistent: 148 SMs x 2 CTAs
#define BK    64                     // K halves per chunk (128B rows)
#define NCHUNK (KDIM / BK)           // 4

#define PITCH_H 72                           // halves per smem row (144B)
#define ROW_B   144                          // bytes per smem row
#define TILE_B  (BM * ROW_B)                 // 18432 B per tile
#define STAGE_B (2 * TILE_B)                 // A + B = 36864 B per stage
#define SD_OFF  (2 * STAGE_B)                // 73728: mirror staging buffer
#define SD_PITCH 132                         // floats
#define SMEM_BYTES (SD_OFF + 64 * SD_PITCH * 4)   // 107520 B

__device__ float          g_norms[BATCH * SEQ];
__device__ __nv_bfloat16  g_xbf[BATCH * SEQ * KDIM];   // 8.4 MB bf16 copy

// ---------------------------------------------------------------------------
// PTX helpers (sm_80-era only: must compile for plain compute_100)
// ---------------------------------------------------------------------------
__device__ __forceinline__ uint32_t smem_u32(const void* p) {
    uint32_t a;
    asm("{ .reg .u64 t; cvta.to.shared.u64 t, %1; cvt.u32.u64 %0, t; }"
        : "=r"(a) : "l"(p));
    return a;
}
__device__ __forceinline__ void cp16(uint32_t dst, const void* src) {
    asm volatile("cp.async.cg.shared.global [%0], [%1], 16;"
                 :: "r"(dst), "l"(src) : "memory");
}
#define CP_COMMIT() asm volatile("cp.async.commit_group;" ::: "memory")
#define CP_WAIT(n)  asm volatile("cp.async.wait_group %0;" :: "n"(n) : "memory")

__device__ __forceinline__ void ldsm_x4(uint32_t addr, uint32_t* r) {
    asm volatile("ldmatrix.sync.aligned.m8n8.x4.shared.b16 {%0,%1,%2,%3}, [%4];"
                 : "=r"(r[0]), "=r"(r[1]), "=r"(r[2]), "=r"(r[3]) : "r"(addr));
}
__device__ __forceinline__ void mma_bf16(float* c, const uint32_t* a,
                                         const uint32_t* b) {
    asm volatile(
        "mma.sync.aligned.m16n8k16.row.col.f32.bf16.bf16.f32 "
        "{%0,%1,%2,%3}, {%4,%5,%6,%7}, {%8,%9}, {%0,%1,%2,%3};"
        : "+f"(c[0]), "+f"(c[1]), "+f"(c[2]), "+f"(c[3])
        : "r"(a[0]), "r"(a[1]), "r"(a[2]), "r"(a[3]), "r"(b[0]), "r"(b[1]));
}

// ---------------------------------------------------------------------------
// Kernel 1: per-row squared norms (fp32 exact) + bf16 conversion (RN)
// ---------------------------------------------------------------------------
__global__ void norms_conv_kernel(const float* __restrict__ x) {
    int row  = blockIdx.x * 8 + (threadIdx.x >> 5);
    int lane = threadIdx.x & 31;
    if (row >= BATCH * SEQ) return;
    const float4* p = (const float4*)(x + (size_t)row * KDIM);
    float4 v0 = p[2 * lane];
    float4 v1 = p[2 * lane + 1];
    float s = v0.x * v0.x + v0.y * v0.y + v0.z * v0.z + v0.w * v0.w +
              v1.x * v1.x + v1.y * v1.y + v1.z * v1.z + v1.w * v1.w;

    __nv_bfloat162 h[4];
    h[0] = __floats2bfloat162_rn(v0.x, v0.y);
    h[1] = __floats2bfloat162_rn(v0.z, v0.w);
    h[2] = __floats2bfloat162_rn(v1.x, v1.y);
    h[3] = __floats2bfloat162_rn(v1.z, v1.w);
    *(uint4*)(g_xbf + (size_t)row * KDIM + lane * 8) = *(const uint4*)h;

#pragma unroll
    for (int o = 16; o; o >>= 1) s += __shfl_xor_sync(0xffffffffu, s, o);
    if (lane == 0) g_norms[row] = s;
}

// ---------------------------------------------------------------------------
// decode work item -> (b, ti, tj)
// ---------------------------------------------------------------------------
__device__ __forceinline__ void decode_work(int work, int& b, int& ti, int& tj) {
    b = work / NPAIR;
    int p = work % NPAIR;
    ti = 0;
    while (p >= NT - ti) { p -= NT - ti; ti++; }
    tj = ti + p;
}

// ---------------------------------------------------------------------------
// Kernel 2: persistent bf16 mma.sync Gram + fp32 distance epilogue,
// software-pipelined ACROSS work items: next item's chunk0/1 cp.async is
// issued before this item's epilogue, so stores overlap next loads.
// ---------------------------------------------------------------------------
__global__ __launch_bounds__(256, 2)
void dist_mma(float* __restrict__ out) {
    extern __shared__ float smf[];
    __shared__ float s_ni[BM], s_nj[BM];
    const uint32_t smb = smem_u32(smf);

    const int tid  = threadIdx.x;
    const int lane = tid & 31;
    const int w    = tid >> 5;
    const int wm   = w & 1;          // warp row (2 x 64)
    const int wn   = w >> 1;         // warp col (4 x 32)
    const int gid  = lane >> 2;      // 0..7
    const int tig  = lane & 3;       // 0..3

    const uint32_t aoff = (uint32_t)(
        ((lane & 15) * PITCH_H + ((lane >> 4) & 1) * 8) * 2);
    const uint32_t boff4 = (uint32_t)(
        (((lane & 7) + 8 * ((lane >> 4) & 1)) * PITCH_H +
         ((lane >> 3) & 1) * 8) * 2);

    // loader thread mapping
    const int lrow = tid >> 3;           // base row (x4 passes of 32)
    const int lg   = tid & 7;            // 16B granule

    auto load_chunk = [&](const __nv_bfloat16* xb, int i0, int j0, int c, int s) {
        const uint32_t base = smb + (uint32_t)s * STAGE_B;
#pragma unroll
        for (int t = 0; t < 4; t++) {
            const int row = lrow + t * 32;
            const uint32_t off = (uint32_t)(row * ROW_B + lg * 16);
            cp16(base + off,
                 xb + (size_t)(i0 + row) * KDIM + c * BK + lg * 8);
            cp16(base + TILE_B + off,
                 xb + (size_t)(j0 + row) * KDIM + c * BK + lg * 8);
        }
        CP_COMMIT();
    };

    int work = blockIdx.x;
    int b, ti, tj;
    if (work < NWORK) {
        decode_work(work, b, ti, tj);
        const __nv_bfloat16* xb = g_xbf + (size_t)b * SEQ * KDIM;
        load_chunk(xb, ti * BM, tj * BM, 0, 0);
        load_chunk(xb, ti * BM, tj * BM, 1, 1);
        // norms for first item
        if (tid < BM) s_ni[tid] = g_norms[b * SEQ + ti * BM + tid];
        else          s_nj[tid - BM] = g_norms[b * SEQ + tj * BM + tid - BM];
    }

    while (work < NWORK) {
        const int i0 = ti * BM, j0 = tj * BM;
        const bool diag = (ti == tj);
        const __nv_bfloat16* xb = g_xbf + (size_t)b * SEQ * KDIM;
        float* ob = out + (size_t)b * SEQ * SEQ;

        float acc[4][4][4];
#pragma unroll
        for (int mt = 0; mt < 4; mt++)
#pragma unroll
            for (int nt = 0; nt < 4; nt++)
#pragma unroll
                for (int q = 0; q < 4; q++) acc[mt][nt][q] = 0.f;

        // ---------------- mainloop: 4 chunks, 2-stage pipeline -------------
        for (int c = 0; c < NCHUNK; c++) {
            if (c < NCHUNK - 1) { CP_WAIT(1); } else { CP_WAIT(0); }
            __syncthreads();

            const uint32_t As_u = smb +
                (uint32_t)((c & 1) * STAGE_B + wm * 64 * ROW_B) + aoff;
            const uint32_t Bs_u = smb +
                (uint32_t)((c & 1) * STAGE_B + TILE_B + wn * 32 * ROW_B) + boff4;

#pragma unroll
            for (int kk = 0; kk < 4; kk++) {
                uint32_t af[4][4], bf[4][2];
#pragma unroll
                for (int mt = 0; mt < 4; mt++)
                    ldsm_x4(As_u + (uint32_t)(mt * 16 * ROW_B + kk * 32),
                            af[mt]);
#pragma unroll
                for (int nt = 0; nt < 4; nt += 2) {
                    uint32_t r4[4];
                    ldsm_x4(Bs_u + (uint32_t)(nt * 8 * ROW_B + kk * 32), r4);
                    bf[nt][0]     = r4[0];
                    bf[nt][1]     = r4[1];
                    bf[nt + 1][0] = r4[2];
                    bf[nt + 1][1] = r4[3];
                }
#pragma unroll
                for (int mt = 0; mt < 4; mt++)
#pragma unroll
                    for (int nt = 0; nt < 4; nt++)
                        mma_bf16(acc[mt][nt], af[mt], bf[nt]);
            }
            if (c + 2 < NCHUNK) {
                __syncthreads();
                load_chunk(xb, i0, j0, c + 2, c & 1);
            }
        }
        __syncthreads();   // all stage reads of this item complete

        // ------- acc -> distances (consumes s_ni/s_nj), diag zeroed --------
#pragma unroll
        for (int mt = 0; mt < 4; mt++) {
            const int r0 = wm * 64 + mt * 16 + gid;
            const int r1 = r0 + 8;
            const float n0 = s_ni[r0], n1 = s_ni[r1];
#pragma unroll
            for (int nt = 0; nt < 4; nt++) {
                const int jc = wn * 32 + nt * 8 + tig * 2;
                const float m0 = s_nj[jc], m1 = s_nj[jc + 1];
                float d00 = fmaxf(n0 + m0 - 2.f * acc[mt][nt][0], 0.f);
                float d01 = fmaxf(n0 + m1 - 2.f * acc[mt][nt][1], 0.f);
                float d10 = fmaxf(n1 + m0 - 2.f * acc[mt][nt][2], 0.f);
                float d11 = fmaxf(n1 + m1 - 2.f * acc[mt][nt][3], 0.f);
                if (diag) {
                    if (r0 == jc)     d00 = 0.f;
                    if (r0 == jc + 1) d01 = 0.f;
                    if (r1 == jc)     d10 = 0.f;
                    if (r1 == jc + 1) d11 = 0.f;
                }
                acc[mt][nt][0] = d00; acc[mt][nt][1] = d01;
                acc[mt][nt][2] = d10; acc[mt][nt][3] = d11;
            }
        }

        // ------- prefetch NEXT work item's chunk 0/1 into the stages -------
        const int nxt = work + GRID_P;
        int nb = 0, nti = 0, ntj = 0;
        if (nxt < NWORK) {
            decode_work(nxt, nb, nti, ntj);
            const __nv_bfloat16* nxb = g_xbf + (size_t)nb * SEQ * KDIM;
            load_chunk(nxb, nti * BM, ntj * BM, 0, 0);
            load_chunk(nxb, nti * BM, ntj * BM, 1, 1);
        }

        // ------- normal orientation: direct float2 stores ------------------
#pragma unroll
        for (int mt = 0; mt < 4; mt++) {
            const int r0 = wm * 64 + mt * 16 + gid;
#pragma unroll
            for (int nt = 0; nt < 4; nt++) {
                const int jc = wn * 32 + nt * 8 + tig * 2;
                *(float2*)(ob + (size_t)(i0 + r0) * SEQ + j0 + jc) =
                    make_float2(acc[mt][nt][0], acc[mt][nt][1]);
                *(float2*)(ob + (size_t)(i0 + r0 + 8) * SEQ + j0 + jc) =
                    make_float2(acc[mt][nt][2], acc[mt][nt][3]);
            }
        }

        __syncthreads();   // all threads past the s_ni/s_nj reads

        // ------- norms for next item (overlaps mirror epilogue) ------------
        if (nxt < NWORK) {
            if (tid < BM) s_ni[tid] = g_norms[nb * SEQ + nti * BM + tid];
            else          s_nj[tid - BM] = g_norms[nb * SEQ + ntj * BM + tid - BM];
        }

        // ------- mirror orientation: two 64-col half-passes via sd ---------
        if (!diag) {
            float* sd = smf + SD_OFF / 4;   // 64 x 132 floats
#pragma unroll
            for (int hh = 0; hh < 2; hh++) {
                if ((wn >> 1) == hh) {      // warps owning cols hh*64..
#pragma unroll
                    for (int mt = 0; mt < 4; mt++) {
                        const int r0 = wm * 64 + mt * 16 + gid;
#pragma unroll
                        for (int nt = 0; nt < 4; nt++) {
                            const int jl = (wn & 1) * 32 + nt * 8 + tig * 2;
                            sd[jl * SD_PITCH + r0]           = acc[mt][nt][0];
                            sd[(jl + 1) * SD_PITCH + r0]     = acc[mt][nt][1];
                            sd[jl * SD_PITCH + r0 + 8]       = acc[mt][nt][2];
                            sd[(jl + 1) * SD_PITCH + r0 + 8] = acc[mt][nt][3];
                        }
                    }
                }
                __syncthreads();
#pragma unroll
                for (int rr = 0; rr < 8; rr++) {
                    const int jl = w * 8 + rr;          // 0..63
                    float4 v = *(const float4*)(sd + jl * SD_PITCH + lane * 4);
                    *(float4*)(ob + (size_t)(j0 + hh * 64 + jl) * SEQ +
                               i0 + lane * 4) = v;
                }
                if (hh == 0) __syncthreads();  // before overwriting sd
            }
        }

        work = nxt; b = nb; ti = nti; tj = ntj;
    }
}

// ---------------------------------------------------------------------------
extern "C" void kernel_launch(void* const* d_in, const int* in_sizes, int n_in,
                              void* d_out, int out_size) {
    const float* x = (const float*)d_in[0];
    float* out = (float*)d_out;
    (void)in_sizes; (void)n_in; (void)out_size;

    cudaFuncSetAttribute(dist_mma, cudaFuncAttributeMaxDynamicSharedMemorySize,
                         SMEM_BYTES);
    norms_conv_kernel<<<(BATCH * SEQ + 7) / 8, 256>>>(x);
    dist_mma<<<GRID_P, 256, SMEM_BYTES>>>(out);
}